// round 17
// baseline (speedup 1.0000x reference)
#include <cuda_runtime.h>
#include <cstdint>

#define Bdim 4
#define Hdim 32
#define Tdim 2048
#define Kdim 64
#define Vdim 64
#define SEGLEN 1024
#define CHUNK 16
#define NCHUNK (SEGLEN / CHUNK)     // 64
#define NTHREADS 512
#define CHUNK_BYTES (CHUNK * Kdim * 4)   // 4096 B per tensor per chunk per half

// scratch (static device arrays; no allocation)
__device__ float g_qe[(size_t)Bdim * Hdim * SEGLEN * Kdim];   // q ⊙ e^{c} for seg-1
__device__ float g_smid[(size_t)Bdim * Hdim * Kdim * Vdim];   // state after seg-0
__device__ float g_b1[(size_t)Bdim * Hdim * Kdim * Vdim];     // seg-1 scan from zero
__device__ float g_dend[(size_t)Bdim * Hdim * Kdim];          // e^{sum w} over seg-1

// ---- packed f32x2 helpers (sm_103a FFMA2 path) ----
__device__ __forceinline__ float2 fma2(float2 a, float2 b, float2 c) {
    float2 d;
    asm("fma.rn.f32x2 %0, %1, %2, %3;"
        : "=l"(reinterpret_cast<unsigned long long&>(d))
        : "l"(reinterpret_cast<unsigned long long&>(a)),
          "l"(reinterpret_cast<unsigned long long&>(b)),
          "l"(reinterpret_cast<unsigned long long&>(c)));
    return d;
}
__device__ __forceinline__ float2 mul2(float2 a, float2 b) {
    float2 d;
    asm("mul.rn.f32x2 %0, %1, %2;"
        : "=l"(reinterpret_cast<unsigned long long&>(d))
        : "l"(reinterpret_cast<unsigned long long&>(a)),
          "l"(reinterpret_cast<unsigned long long&>(b)));
    return d;
}
__device__ __forceinline__ void cp16(uint32_t smem_dst, const void* gmem_src) {
    asm volatile("cp.async.cg.shared.global [%0], [%1], 16;"
                 :: "r"(smem_dst), "l"(gmem_src));
}

// Kernel 1: block = one (b,h); two 256-thread halves scan the two T-segments
// concurrently (seg 0 from h0 -> o + g_smid; seg 1 from 0 -> o' + g_b1 + g_qe/g_dend).
// Each half: ks = htid&15 (K 16x4), vg = htid>>4 (V 16x4); 4k x 4v register tile;
// per step o_v = sum_k q_k*S_kv + v_v*sum_k(q u k); per-step xor8+xor4 shfl,
// xor2/xor1 + store batched over 4 steps (value-distribution butterfly).
__global__ __launch_bounds__(NTHREADS, 1)
void rwkv6_scan_seg_kernel(const float* __restrict__ r,
                           const float* __restrict__ kin,
                           const float* __restrict__ vin,
                           const float* __restrict__ win,
                           const float* __restrict__ uin,
                           const float* __restrict__ h0,
                           float* __restrict__ o) {
    const int bh    = blockIdx.x;
    const int h     = bh % Hdim;
    const int tid   = threadIdx.x;
    const int half  = tid >> 8;          // segment id
    const int htid  = tid & 255;
    const int ks    = htid & 15;
    const int vg    = htid >> 4;
    const int kbase = ks * 4;
    const int vbase = vg * 4;
    const bool b3   = (ks & 8) != 0;
    const bool b2   = (ks & 4) != 0;
    const bool c1   = (ks & 2) != 0;
    const bool c0   = (ks & 1) != 0;
    const int vidx  = vbase + (b3 ? 2 : 0) + (b2 ? 1 : 0);

    __shared__ float sq[2][2][CHUNK][Kdim];   // [half][buf]
    __shared__ float sk[2][2][CHUNK][Kdim];
    __shared__ float sw[2][2][CHUNK][Kdim];   // exp() applied in place per chunk
    __shared__ float sv[2][2][CHUNK][Vdim];
    __shared__ float squk[2][2][CHUNK];
    __shared__ float su[Kdim];

    // state tile: s[v*2+p] holds S[kbase+2p .. +1][vbase+v]
    float2 s[8];
    if (half == 0) {
        const size_t hb = (size_t)bh * Kdim * Vdim;
#pragma unroll
        for (int v = 0; v < 4; v++)
#pragma unroll
            for (int p = 0; p < 2; p++) {
                s[v * 2 + p].x = h0[hb + (size_t)(kbase + 2 * p)     * Vdim + vbase + v];
                s[v * 2 + p].y = h0[hb + (size_t)(kbase + 2 * p + 1) * Vdim + vbase + v];
            }
    } else {
#pragma unroll
        for (int j = 0; j < 8; j++) s[j] = make_float2(0.f, 0.f);
    }
    if (tid < Kdim) su[tid] = uin[h * Kdim + tid];

    float c_acc = 0.f;   // seg-1, htid<64: running cumsum of w for its k

    const size_t base  = (size_t)bh * Tdim * Kdim + (size_t)half * SEGLEN * Kdim;
    const size_t qeb   = (size_t)bh * SEGLEN * Kdim;   // seg-1 qe scratch base

    const uint32_t sq_s = (uint32_t)__cvta_generic_to_shared(&sq[half][0][0][0]);
    const uint32_t sk_s = (uint32_t)__cvta_generic_to_shared(&sk[half][0][0][0]);
    const uint32_t sw_s = (uint32_t)__cvta_generic_to_shared(&sw[half][0][0][0]);
    const uint32_t sv_s = (uint32_t)__cvta_generic_to_shared(&sv[half][0][0][0]);

    auto issue_chunk = [&](int c, int buf) {
        const size_t off = base + (size_t)c * CHUNK * Kdim;
        const uint32_t so = buf * CHUNK_BYTES + htid * 16;
        const size_t go = off + htid * 4;
        cp16(sq_s + so, r   + go);
        cp16(sk_s + so, kin + go);
        cp16(sw_s + so, win + go);
        cp16(sv_s + so, vin + go);
        asm volatile("cp.async.commit_group;");
    };

    issue_chunk(0, 0);
    issue_chunk(1, 1);

#pragma unroll 1
    for (int c = 0; c < NCHUNK; c++) {
        const int cur = c & 1;
        asm volatile("cp.async.wait_group 1;");
        __syncthreads();

        // ---- per-chunk preprocessing ----
        if (half == 0) {
            // exp(w) in place: 1024 values / 256 threads = one float4 each
            float4* wf = (float4*)&sw[0][cur][0][0];
            float4 t = wf[htid];
            t.x = __expf(t.x); t.y = __expf(t.y);
            t.z = __expf(t.z); t.w = __expf(t.w);
            wf[htid] = t;
        } else if (htid < Kdim) {
            // seg-1: cumsum(w) per k (exclusive prefix), qe store, exp(w) in place
            const int k = htid;
            float cc = c_acc;
#pragma unroll
            for (int tt = 0; tt < CHUNK; tt++) {
                const float wraw = sw[1][cur][tt][k];
                g_qe[qeb + (size_t)(c * CHUNK + tt) * Kdim + k] =
                    sq[1][cur][tt][k] * __expf(cc);
                cc += wraw;
                sw[1][cur][tt][k] = __expf(wraw);
            }
            c_acc = cc;
        }
        // quk[t] = sum_k q*u*k : 16 steps x 16 lanes, 4 k's each (both halves)
        {
            const int stp  = htid >> 4;
            const int part = htid & 15;
            const float4 q4 = *(const float4*)&sq[half][cur][stp][part * 4];
            const float4 k4 = *(const float4*)&sk[half][cur][stp][part * 4];
            const float4 u4 = *(const float4*)&su[part * 4];
            float sum = q4.x * k4.x * u4.x;
            sum = fmaf(q4.y * k4.y, u4.y, sum);
            sum = fmaf(q4.z * k4.z, u4.z, sum);
            sum = fmaf(q4.w * k4.w, u4.w, sum);
            sum += __shfl_xor_sync(0xffffffffu, sum, 1);
            sum += __shfl_xor_sync(0xffffffffu, sum, 2);
            sum += __shfl_xor_sync(0xffffffffu, sum, 4);
            sum += __shfl_xor_sync(0xffffffffu, sum, 8);
            if (part == 0) squk[half][cur][stp] = sum;
        }
        __syncthreads();

        // ---- compute CHUNK steps in batches of 4, no barriers ----
        const size_t obase = (size_t)bh * Tdim * Vdim
                           + (size_t)half * SEGLEN * Vdim
                           + (size_t)c * CHUNK * Vdim;
#pragma unroll 2
        for (int tb = 0; tb < CHUNK; tb += 4) {
            float P[4];
#pragma unroll
            for (int t4 = 0; t4 < 4; t4++) {
                const int tt = tb + t4;
                const float4 q4 = *(const float4*)&sq[half][cur][tt][kbase];
                const float4 k4 = *(const float4*)&sk[half][cur][tt][kbase];
                const float4 e4 = *(const float4*)&sw[half][cur][tt][kbase];
                const float4 v4 = *(const float4*)&sv[half][cur][tt][vbase];

                const float2 q2a = make_float2(q4.x, q4.y);
                const float2 q2b = make_float2(q4.z, q4.w);
                const float2 k2a = make_float2(k4.x, k4.y);
                const float2 k2b = make_float2(k4.z, k4.w);
                const float2 e2a = make_float2(e4.x, e4.y);
                const float2 e2b = make_float2(e4.z, e4.w);
                const float vs[4] = {v4.x, v4.y, v4.z, v4.w};

                float a[4];
#pragma unroll
                for (int v = 0; v < 4; v++) {
                    const float2 vv = make_float2(vs[v], vs[v]);
                    const float2 kva = mul2(k2a, vv);
                    const float2 kvb = mul2(k2b, vv);
                    float2 acc = mul2(q2a, s[v * 2 + 0]);
                    acc = fma2(q2b, s[v * 2 + 1], acc);
                    s[v * 2 + 0] = fma2(s[v * 2 + 0], e2a, kva);
                    s[v * 2 + 1] = fma2(s[v * 2 + 1], e2b, kvb);
                    a[v] = acc.x + acc.y;
                }

                const float sx = b3 ? a[0] : a[2];
                const float sy = b3 ? a[1] : a[3];
                const float rx = __shfl_xor_sync(0xffffffffu, sx, 8);
                const float ry = __shfl_xor_sync(0xffffffffu, sy, 8);
                const float p0 = (b3 ? a[2] : a[0]) + rx;
                const float p1 = (b3 ? a[3] : a[1]) + ry;
                const float snd = b2 ? p0 : p1;
                const float rz = __shfl_xor_sync(0xffffffffu, snd, 4);
                P[t4] = (b2 ? p1 : p0) + rz;
            }
            // batched tail: sum over 4 c-lanes while distributing the 4 steps
            const float s0 = c1 ? P[0] : P[2];
            const float s1 = c1 ? P[1] : P[3];
            const float q0 = (c1 ? P[2] : P[0]) + __shfl_xor_sync(0xffffffffu, s0, 2);
            const float q1 = (c1 ? P[3] : P[1]) + __shfl_xor_sync(0xffffffffu, s1, 2);
            const float snd2 = c0 ? q0 : q1;
            const float red = (c0 ? q1 : q0) + __shfl_xor_sync(0xffffffffu, snd2, 1);

            const int tsel = tb + (ks & 3);
            o[obase + (size_t)tsel * Vdim + vidx] =
                fmaf(squk[half][cur][tsel], sv[half][cur][tsel][vidx], red);
        }

        __syncthreads();
        if (c + 2 < NCHUNK)
            issue_chunk(c + 2, cur);
    }

    // segment-final states -> scratch
    {
        float* dst = (half == 0) ? g_smid : g_b1;
        const size_t hb = (size_t)bh * Kdim * Vdim;
#pragma unroll
        for (int v = 0; v < 4; v++)
#pragma unroll
            for (int p = 0; p < 2; p++) {
                dst[hb + (size_t)(kbase + 2 * p)     * Vdim + vbase + v] = s[v * 2 + p].x;
                dst[hb + (size_t)(kbase + 2 * p + 1) * Vdim + vbase + v] = s[v * 2 + p].y;
            }
    }
    if (half == 1 && htid < Kdim)
        g_dend[bh * Kdim + htid] = __expf(c_acc);
}

// Kernel 2: o[second half] += qe @ S_mid ;  hT = dend ⊙ S_mid + B1.
// grid = 128 bh x 8 row-tiles (128 rows each), 256 threads.
__global__ __launch_bounds__(256, 2)
void rwkv6_fixup_kernel(float* __restrict__ o, float* __restrict__ hT) {
    const int bh   = blockIdx.x >> 3;
    const int tile = blockIdx.x & 7;
    const int tid  = threadIdx.x;

    __shared__ float sS[Kdim][Vdim];   // 16 KB
    {
        const float* src = g_smid + (size_t)bh * Kdim * Vdim;
        float4* d = (float4*)&sS[0][0];
        const float4* s4 = (const float4*)src;
#pragma unroll
        for (int i = 0; i < 4; i++) d[tid + i * 256] = s4[tid + i * 256];
    }
    __syncthreads();

    // 2 threads per row: row = tile*128 + (tid>>1); each covers 32 v's.
    const int row = tile * 128 + (tid >> 1);
    const int vh  = (tid & 1) * 32;

    // load qe row (64 floats)
    float4 qr[16];
    {
        const float4* q4 = (const float4*)(g_qe + ((size_t)bh * SEGLEN + row) * Kdim);
#pragma unroll
        for (int i = 0; i < 16; i++) qr[i] = q4[i];
    }

    float2 acc[16];
#pragma unroll
    for (int j = 0; j < 16; j++) acc[j] = make_float2(0.f, 0.f);

#pragma unroll 4
    for (int kq = 0; kq < 16; kq++) {
        const float kv[4] = {qr[kq].x, qr[kq].y, qr[kq].z, qr[kq].w};
#pragma unroll
        for (int kk = 0; kk < 4; kk++) {
            const int k = kq * 4 + kk;
            const float2 qv = make_float2(kv[kk], kv[kk]);
            const float2* srow = (const float2*)&sS[k][vh];
#pragma unroll
            for (int j = 0; j < 16; j++)
                acc[j] = fma2(qv, srow[j], acc[j]);
        }
    }

    // o += acc  (second-half rows)
    {
        float* orow = o + ((size_t)bh * Tdim + SEGLEN + row) * Vdim + vh;
        float4* o4 = (float4*)orow;
#pragma unroll
        for (int j = 0; j < 8; j++) {
            float4 t = o4[j];
            t.x += acc[2 * j].x;     t.y += acc[2 * j].y;
            t.z += acc[2 * j + 1].x; t.w += acc[2 * j + 1].y;
            o4[j] = t;
        }
    }

    // tile 0: final state hT = dend ⊙ S_mid + B1
    if (tile == 0) {
        const size_t hb = (size_t)bh * Kdim * Vdim;
#pragma unroll
        for (int i = 0; i < 4; i++) {
            const int cell = tid * 16 + i * 4;         // float4 granularity
            const int k = cell >> 6;
            const float d = g_dend[bh * Kdim + k];
            const float4 sm = *(const float4*)&g_smid[hb + cell];
            const float4 b1 = *(const float4*)&g_b1[hb + cell];
            float4 out;
            out.x = fmaf(d, sm.x, b1.x);
            out.y = fmaf(d, sm.y, b1.y);
            out.z = fmaf(d, sm.z, b1.z);
            out.w = fmaf(d, sm.w, b1.w);
            *(float4*)&hT[hb + cell] = out;
        }
    }
}

extern "C" void kernel_launch(void* const* d_in, const int* in_sizes, int n_in,
                              void* d_out, int out_size) {
    const float* r  = (const float*)d_in[0];
    const float* k  = (const float*)d_in[1];
    const float* v  = (const float*)d_in[2];
    const float* w  = (const float*)d_in[3];
    const float* u  = (const float*)d_in[4];
    const float* h0 = (const float*)d_in[5];

    float* o  = (float*)d_out;
    float* hT = o + (size_t)Bdim * Hdim * Tdim * Vdim;

    rwkv6_scan_seg_kernel<<<Bdim * Hdim, NTHREADS>>>(r, k, v, w, u, h0, o);
    rwkv6_fixup_kernel<<<Bdim * Hdim * 8, 256>>>(o, hT);
}